// round 12
// baseline (speedup 1.0000x reference)
#include <cuda_runtime.h>
#include <cuda_fp16.h>

#define SH 16
#define SW 16
#define SL 8
#define NCOEF 12
#define GRID_ELEMS (SH * SW * SL * NCOEF)        // 24576 halfs per copy
// Copy B at +GRID_ELEMS+20 halfs: odd-z0 records are 16B-aligned there; the
// +10-word rotation keeps the two copies' record lattices on disjoint quads.
#define COPY_B_OFF (GRID_ELEMS + 20)
#define SMEM_HALFS (COPY_B_OFF + GRID_ELEMS)
#define SMEM_BYTES (SMEM_HALFS * 2)              // 98344 B -> 2 CTAs/SM

__device__ __forceinline__ __half2 as_h2(unsigned int u) {
    return *reinterpret_cast<__half2*>(&u);
}

struct PixPrep {
    const __half* base;   // 16B-aligned record base in the parity copy
    float wx0, wx1, wy0, wy1, wz0, wz1;
};

__device__ __forceinline__ PixPrep prep_pixel(
    const __half* __restrict__ sg, float r, float g, float b,
    float cxv, float cyv)
{
    const float guide = 0.2126f * r + 0.7152f * g + 0.0722f * b;
    const float gx = fminf(fmaxf(cxv * (float)(SW - 1), 0.0f), (float)SW - 1.001f);
    const float gy = fminf(fmaxf(cyv * (float)(SH - 1), 0.0f), (float)SH - 1.001f);
    const float gcl = fminf(fmaxf(guide, 0.0f), 1.0f);
    const float gz = fminf(fmaxf(gcl * (float)(SL - 1), 0.0f), (float)SL - 1.001f);

    const int x0 = (int)gx;
    const int y0 = (int)gy;
    const int z0 = (int)gz;

    PixPrep pp;
    pp.wx1 = gx - (float)x0;  pp.wx0 = 1.0f - pp.wx1;
    pp.wy1 = gy - (float)y0;  pp.wy0 = 1.0f - pp.wy1;
    pp.wz1 = gz - (float)z0;  pp.wz0 = 1.0f - pp.wz1;
    pp.base = sg + ((z0 & 1) ? COPY_B_OFF : 0)
            + (((y0 << 4) + x0) * SL + z0) * NCOEF;
    return pp;
}

// Process TWO pixels with corner-interleaved LDS streams: per spatial corner,
// 6 LDS.128 are issued back-to-back (3 per pixel) before any HFMA2 consumes
// them, keeping the l1tex wavefront queue full through the FMA bursts.
__device__ __forceinline__ void process_pixel_pair(
    const __half* __restrict__ sg,
    float rA, float gA, float bA, float cxA, float cyA,
    float rB, float gB, float bB, float cxB, float cyB,
    float* __restrict__ o)   // o[0..5]
{
    const PixPrep A = prep_pixel(sg, rA, gA, bA, cxA, cyA);
    const PixPrep B = prep_pixel(sg, rB, gB, bB, cxB, cyB);

    __half2 zero = __float2half2_rn(0.f);
    __half2 aA0 = zero, aA1 = zero, aA2 = zero, aA3 = zero, aA4 = zero, aA5 = zero;
    __half2 aB0 = zero, aB1 = zero, aB2 = zero, aB3 = zero, aB4 = zero, aB5 = zero;

    #pragma unroll
    for (int dy = 0; dy < 2; ++dy) {
        const float wyA = dy ? A.wy1 : A.wy0;
        const float wyB = dy ? B.wy1 : B.wy0;
        #pragma unroll
        for (int dx = 0; dx < 2; ++dx) {
            const int off = dy * (SW * SL * NCOEF) + dx * (SL * NCOEF);

            // ---- issue all 6 loads first (independent scoreboard slots) ----
            const uint4* pA = reinterpret_cast<const uint4*>(A.base + off);
            const uint4* pB = reinterpret_cast<const uint4*>(B.base + off);
            const uint4 qa0 = pA[0];
            const uint4 qb0 = pB[0];
            const uint4 qa1 = pA[1];
            const uint4 qb1 = pB[1];
            const uint4 qa2 = pA[2];
            const uint4 qb2 = pB[2];

            const float wxyA = wyA * (dx ? A.wx1 : A.wx0);
            const float wxyB = wyB * (dx ? B.wx1 : B.wx0);
            const __half2 wA0 = __float2half2_rn(wxyA * A.wz0);
            const __half2 wA1 = __float2half2_rn(wxyA * A.wz1);
            const __half2 wB0 = __float2half2_rn(wxyB * B.wz0);
            const __half2 wB1 = __float2half2_rn(wxyB * B.wz1);

            // ---- consume A ----
            aA0 = __hfma2(wA0, as_h2(qa0.x), aA0);
            aA1 = __hfma2(wA0, as_h2(qa0.y), aA1);
            aA2 = __hfma2(wA0, as_h2(qa0.z), aA2);
            aA3 = __hfma2(wA0, as_h2(qa0.w), aA3);
            aA4 = __hfma2(wA0, as_h2(qa1.x), aA4);
            aA5 = __hfma2(wA0, as_h2(qa1.y), aA5);
            aA0 = __hfma2(wA1, as_h2(qa1.z), aA0);
            aA1 = __hfma2(wA1, as_h2(qa1.w), aA1);
            aA2 = __hfma2(wA1, as_h2(qa2.x), aA2);
            aA3 = __hfma2(wA1, as_h2(qa2.y), aA3);
            aA4 = __hfma2(wA1, as_h2(qa2.z), aA4);
            aA5 = __hfma2(wA1, as_h2(qa2.w), aA5);

            // ---- consume B ----
            aB0 = __hfma2(wB0, as_h2(qb0.x), aB0);
            aB1 = __hfma2(wB0, as_h2(qb0.y), aB1);
            aB2 = __hfma2(wB0, as_h2(qb0.z), aB2);
            aB3 = __hfma2(wB0, as_h2(qb0.w), aB3);
            aB4 = __hfma2(wB0, as_h2(qb1.x), aB4);
            aB5 = __hfma2(wB0, as_h2(qb1.y), aB5);
            aB0 = __hfma2(wB1, as_h2(qb1.z), aB0);
            aB1 = __hfma2(wB1, as_h2(qb1.w), aB1);
            aB2 = __hfma2(wB1, as_h2(qb2.x), aB2);
            aB3 = __hfma2(wB1, as_h2(qb2.y), aB3);
            aB4 = __hfma2(wB1, as_h2(qb2.z), aB4);
            aB5 = __hfma2(wB1, as_h2(qb2.w), aB5);
        }
    }

    {
        const float2 f0 = __half22float2(aA0);
        const float2 f1 = __half22float2(aA1);
        const float2 f2 = __half22float2(aA2);
        const float2 f3 = __half22float2(aA3);
        const float2 f4 = __half22float2(aA4);
        const float2 f5 = __half22float2(aA5);
        o[0] = f0.x * rA + f0.y * gA + f1.x * bA + f1.y;
        o[1] = f2.x * rA + f2.y * gA + f3.x * bA + f3.y;
        o[2] = f4.x * rA + f4.y * gA + f5.x * bA + f5.y;
    }
    {
        const float2 f0 = __half22float2(aB0);
        const float2 f1 = __half22float2(aB1);
        const float2 f2 = __half22float2(aB2);
        const float2 f3 = __half22float2(aB3);
        const float2 f4 = __half22float2(aB4);
        const float2 f5 = __half22float2(aB5);
        o[3] = f0.x * rB + f0.y * gB + f1.x * bB + f1.y;
        o[4] = f2.x * rB + f2.y * gB + f3.x * bB + f3.y;
        o[5] = f4.x * rB + f4.y * gB + f5.x * bB + f5.y;
    }
}

__global__ void __launch_bounds__(256, 2)
bilateral_grid_pp_kernel(const float* __restrict__ pixels,
                         const float* __restrict__ coords,
                         const float* __restrict__ grid,
                         float* __restrict__ out,
                         int N)
{
    extern __shared__ __half sg[];

    // Convert fp32 grid -> fp16, write BOTH copies.
    {
        const float2* g2 = reinterpret_cast<const float2*>(grid);
        __half2* a2 = reinterpret_cast<__half2*>(sg);
        __half2* b2 = reinterpret_cast<__half2*>(sg + COPY_B_OFF);
        #pragma unroll 4
        for (int i = threadIdx.x; i < GRID_ELEMS / 2; i += 256) {
            const __half2 v = __float22half2_rn(g2[i]);
            a2[i] = v;
            b2[i] = v;
        }
    }
    __syncthreads();

    const int nb = N >> 1;
    const int stride = gridDim.x * blockDim.x;
    const int tid0 = blockIdx.x * blockDim.x + threadIdx.x;

    for (int bix = tid0; bix < nb; bix += stride) {
        const float2 pa = reinterpret_cast<const float2*>(pixels)[3 * bix + 0];
        const float2 pb = reinterpret_cast<const float2*>(pixels)[3 * bix + 1];
        const float2 pc = reinterpret_cast<const float2*>(pixels)[3 * bix + 2];
        const float4 cd = reinterpret_cast<const float4*>(coords)[bix];

        float o[6];
        process_pixel_pair(sg,
                           pa.x, pa.y, pb.x, cd.x, cd.y,
                           pb.y, pc.x, pc.y, cd.z, cd.w, o);

        float2* o2 = reinterpret_cast<float2*>(out);
        o2[3 * bix + 0] = make_float2(o[0], o[1]);
        o2[3 * bix + 1] = make_float2(o[2], o[3]);
        o2[3 * bix + 2] = make_float2(o[4], o[5]);
    }

    // Tail pixel if N is odd (duplicate into both slots of the pair).
    const int tail_start = nb << 1;
    for (int i = tail_start + tid0; i < N; i += stride) {
        const float r = pixels[3 * i + 0];
        const float g = pixels[3 * i + 1];
        const float b = pixels[3 * i + 2];
        const float cxv = coords[2 * i + 0];
        const float cyv = coords[2 * i + 1];
        float o[6];
        process_pixel_pair(sg, r, g, b, cxv, cyv, r, g, b, cxv, cyv, o);
        out[3 * i + 0] = o[0];
        out[3 * i + 1] = o[1];
        out[3 * i + 2] = o[2];
    }
}

extern "C" void kernel_launch(void* const* d_in, const int* in_sizes, int n_in,
                              void* d_out, int out_size)
{
    const float* pixels = (const float*)d_in[0];   // (B,H,W,3) f32
    const float* coords = (const float*)d_in[1];   // (B,H,W,2) f32
    const float* grid   = (const float*)d_in[2];   // (16,16,8,12) f32
    float* out = (float*)d_out;

    const int N = in_sizes[0] / 3;

    cudaFuncSetAttribute(bilateral_grid_pp_kernel,
                         cudaFuncAttributeMaxDynamicSharedMemorySize, SMEM_BYTES);

    // 2 CTAs/SM x 152 SMs
    const int blocks = 304;
    bilateral_grid_pp_kernel<<<blocks, 256, SMEM_BYTES>>>(pixels, coords, grid, out, N);
}

// round 14
// speedup vs baseline: 1.0487x; 1.0487x over previous
#include <cuda_runtime.h>
#include <cuda_fp16.h>

#define SH 16
#define SW 16
#define SL 8
#define NCOEF 12
#define GRID_ELEMS (SH * SW * SL * NCOEF)        // 24576 halfs per copy
// Copy B at +GRID_ELEMS+20 halfs: odd-z0 records are 16B-aligned there; the
// +10-word rotation keeps the two copies' record lattices on disjoint quads.
#define COPY_B_OFF (GRID_ELEMS + 20)
#define SMEM_HALFS (COPY_B_OFF + GRID_ELEMS)
#define SMEM_BYTES (SMEM_HALFS * 2)              // 98344 B -> 2 CTAs/SM

__device__ __forceinline__ __half2 as_h2(unsigned int u) {
    return *reinterpret_cast<__half2*>(&u);
}

__device__ __forceinline__ void process_pixel(
    const __half* __restrict__ sg,
    float r, float g, float b, float cxv, float cyv,
    float& o0, float& o1, float& o2)
{
    const float guide = 0.2126f * r + 0.7152f * g + 0.0722f * b;
    const float gx = fminf(fmaxf(cxv * (float)(SW - 1), 0.0f), (float)SW - 1.001f);
    const float gy = fminf(fmaxf(cyv * (float)(SH - 1), 0.0f), (float)SH - 1.001f);
    const float gcl = fminf(fmaxf(guide, 0.0f), 1.0f);
    const float gz = fminf(fmaxf(gcl * (float)(SL - 1), 0.0f), (float)SL - 1.001f);

    const int x0 = (int)gx;
    const int y0 = (int)gy;
    const int z0 = (int)gz;
    const float fx = gx - (float)x0;
    const float fy = gy - (float)y0;
    const float fz = gz - (float)z0;
    const float wx0 = 1.0f - fx, wy0 = 1.0f - fy, wz0 = 1.0f - fz;

    const __half* base = sg + ((z0 & 1) ? COPY_B_OFF : 0)
                       + (((y0 << 4) + x0) * SL + z0) * NCOEF;

    __half2 acc0 = __float2half2_rn(0.f), acc1 = acc0, acc2 = acc0;
    __half2 acc3 = acc0, acc4 = acc0, acc5 = acc0;

    #pragma unroll
    for (int dy = 0; dy < 2; ++dy) {
        const float wyv = dy ? fy : wy0;
        #pragma unroll
        for (int dx = 0; dx < 2; ++dx) {
            const float wxy = wyv * (dx ? fx : wx0);
            // 48 B record: z0's 12 halfs then z1's 12 halfs, 16B-aligned.
            const uint4* p4 = reinterpret_cast<const uint4*>(
                base + dy * (SW * SL * NCOEF) + dx * (SL * NCOEF));
            const uint4 q0 = p4[0];
            const uint4 q1 = p4[1];
            const uint4 q2 = p4[2];

            const __half2 w0 = __float2half2_rn(wxy * wz0);
            const __half2 w1 = __float2half2_rn(wxy * fz);

            acc0 = __hfma2(w0, as_h2(q0.x), acc0);
            acc1 = __hfma2(w0, as_h2(q0.y), acc1);
            acc2 = __hfma2(w0, as_h2(q0.z), acc2);
            acc3 = __hfma2(w0, as_h2(q0.w), acc3);
            acc4 = __hfma2(w0, as_h2(q1.x), acc4);
            acc5 = __hfma2(w0, as_h2(q1.y), acc5);

            acc0 = __hfma2(w1, as_h2(q1.z), acc0);
            acc1 = __hfma2(w1, as_h2(q1.w), acc1);
            acc2 = __hfma2(w1, as_h2(q2.x), acc2);
            acc3 = __hfma2(w1, as_h2(q2.y), acc3);
            acc4 = __hfma2(w1, as_h2(q2.z), acc4);
            acc5 = __hfma2(w1, as_h2(q2.w), acc5);
        }
    }

    const float2 f0 = __half22float2(acc0);
    const float2 f1 = __half22float2(acc1);
    const float2 f2 = __half22float2(acc2);
    const float2 f3 = __half22float2(acc3);
    const float2 f4 = __half22float2(acc4);
    const float2 f5 = __half22float2(acc5);

    o0 = f0.x * r + f0.y * g + f1.x * b + f1.y;
    o1 = f2.x * r + f2.y * g + f3.x * b + f3.y;
    o2 = f4.x * r + f4.y * g + f5.x * b + f5.y;
}

__global__ void __launch_bounds__(384, 2)
bilateral_grid_u2_kernel(const float* __restrict__ pixels,
                         const float* __restrict__ coords,
                         const float* __restrict__ grid,
                         float* __restrict__ out,
                         int N)
{
    extern __shared__ __half sg[];

    // Convert fp32 grid -> fp16, write BOTH copies.
    {
        const float2* g2 = reinterpret_cast<const float2*>(grid);
        __half2* a2 = reinterpret_cast<__half2*>(sg);
        __half2* b2 = reinterpret_cast<__half2*>(sg + COPY_B_OFF);
        #pragma unroll 4
        for (int i = threadIdx.x; i < GRID_ELEMS / 2; i += 384) {
            const __half2 v = __float22half2_rn(g2[i]);
            a2[i] = v;
            b2[i] = v;
        }
    }
    __syncthreads();

    const int stride = gridDim.x * blockDim.x;
    const int tid0 = blockIdx.x * blockDim.x + threadIdx.x;

    // Unroll x2 over the grid-stride loop: iteration k+1's global loads
    // (pixels/coords, long-scoreboard) issue inside iteration k's LDS-wait
    // shadow — cross-iteration MLP, the one overlap axis not yet exploited.
    int i = tid0;
    for (; i + stride < N; i += 2 * stride) {
        const int j = i + stride;

        // front-batch both iterations' global loads
        const float r0 = pixels[3 * i + 0];
        const float g0 = pixels[3 * i + 1];
        const float b0 = pixels[3 * i + 2];
        const float2 c0 = reinterpret_cast<const float2*>(coords)[i];
        const float r1 = pixels[3 * j + 0];
        const float g1 = pixels[3 * j + 1];
        const float b1 = pixels[3 * j + 2];
        const float2 c1 = reinterpret_cast<const float2*>(coords)[j];

        float o0, o1, o2;
        process_pixel(sg, r0, g0, b0, c0.x, c0.y, o0, o1, o2);
        out[3 * i + 0] = o0;
        out[3 * i + 1] = o1;
        out[3 * i + 2] = o2;

        float p0, p1, p2;
        process_pixel(sg, r1, g1, b1, c1.x, c1.y, p0, p1, p2);
        out[3 * j + 0] = p0;
        out[3 * j + 1] = p1;
        out[3 * j + 2] = p2;
    }
    // remainder (at most one more element per thread)
    for (; i < N; i += stride) {
        const float r = pixels[3 * i + 0];
        const float g = pixels[3 * i + 1];
        const float b = pixels[3 * i + 2];
        const float2 c = reinterpret_cast<const float2*>(coords)[i];
        float o0, o1, o2;
        process_pixel(sg, r, g, b, c.x, c.y, o0, o1, o2);
        out[3 * i + 0] = o0;
        out[3 * i + 1] = o1;
        out[3 * i + 2] = o2;
    }
}

extern "C" void kernel_launch(void* const* d_in, const int* in_sizes, int n_in,
                              void* d_out, int out_size)
{
    const float* pixels = (const float*)d_in[0];   // (B,H,W,3) f32
    const float* coords = (const float*)d_in[1];   // (B,H,W,2) f32
    const float* grid   = (const float*)d_in[2];   // (16,16,8,12) f32
    float* out = (float*)d_out;

    const int N = in_sizes[0] / 3;

    cudaFuncSetAttribute(bilateral_grid_u2_kernel,
                         cudaFuncAttributeMaxDynamicSharedMemorySize, SMEM_BYTES);

    // 2 CTAs/SM x 152 SMs, 384 threads -> 24 warps/SM, reg cap 85.
    const int blocks = 304;
    bilateral_grid_u2_kernel<<<blocks, 384, SMEM_BYTES>>>(pixels, coords, grid, out, N);
}

// round 15
// speedup vs baseline: 1.0688x; 1.0191x over previous
#include <cuda_runtime.h>
#include <cuda_fp16.h>

#define SH 16
#define SW 16
#define SL 8
#define NCOEF 12
#define GRID_ELEMS (SH * SW * SL * NCOEF)        // 24576 halfs per copy
// Copy B at +GRID_ELEMS+20 halfs: odd-z0 records are 16B-aligned there; the
// +10-word rotation keeps the two copies' record lattices on disjoint quads.
#define COPY_B_OFF (GRID_ELEMS + 20)
#define SMEM_HALFS (COPY_B_OFF + GRID_ELEMS)
#define SMEM_BYTES (SMEM_HALFS * 2)              // 98344 B -> 2 CTAs/SM

__device__ __forceinline__ __half2 as_h2(unsigned int u) {
    return *reinterpret_cast<__half2*>(&u);
}

__device__ __forceinline__ void process_pixel(
    const __half* __restrict__ sg,
    float r, float g, float b, float cxv, float cyv,
    float& o0, float& o1, float& o2)
{
    const float guide = 0.2126f * r + 0.7152f * g + 0.0722f * b;
    const float gx = fminf(fmaxf(cxv * (float)(SW - 1), 0.0f), (float)SW - 1.001f);
    const float gy = fminf(fmaxf(cyv * (float)(SH - 1), 0.0f), (float)SH - 1.001f);
    const float gcl = fminf(fmaxf(guide, 0.0f), 1.0f);
    const float gz = fminf(fmaxf(gcl * (float)(SL - 1), 0.0f), (float)SL - 1.001f);

    const int x0 = (int)gx;
    const int y0 = (int)gy;
    const int z0 = (int)gz;
    const float fx = gx - (float)x0;
    const float fy = gy - (float)y0;
    const float fz = gz - (float)z0;
    const float wx0 = 1.0f - fx, wy0 = 1.0f - fy, wz0 = 1.0f - fz;

    const __half* base = sg + ((z0 & 1) ? COPY_B_OFF : 0)
                       + (((y0 << 4) + x0) * SL + z0) * NCOEF;

    __half2 acc0 = __float2half2_rn(0.f), acc1 = acc0, acc2 = acc0;
    __half2 acc3 = acc0, acc4 = acc0, acc5 = acc0;

    #pragma unroll
    for (int dy = 0; dy < 2; ++dy) {
        const float wyv = dy ? fy : wy0;
        #pragma unroll
        for (int dx = 0; dx < 2; ++dx) {
            const float wxy = wyv * (dx ? fx : wx0);
            // 48 B record: z0's 12 halfs then z1's 12 halfs, 16B-aligned.
            const uint4* p4 = reinterpret_cast<const uint4*>(
                base + dy * (SW * SL * NCOEF) + dx * (SL * NCOEF));
            const uint4 q0 = p4[0];
            const uint4 q1 = p4[1];
            const uint4 q2 = p4[2];

            const __half2 w0 = __float2half2_rn(wxy * wz0);
            const __half2 w1 = __float2half2_rn(wxy * fz);

            acc0 = __hfma2(w0, as_h2(q0.x), acc0);
            acc1 = __hfma2(w0, as_h2(q0.y), acc1);
            acc2 = __hfma2(w0, as_h2(q0.z), acc2);
            acc3 = __hfma2(w0, as_h2(q0.w), acc3);
            acc4 = __hfma2(w0, as_h2(q1.x), acc4);
            acc5 = __hfma2(w0, as_h2(q1.y), acc5);

            acc0 = __hfma2(w1, as_h2(q1.z), acc0);
            acc1 = __hfma2(w1, as_h2(q1.w), acc1);
            acc2 = __hfma2(w1, as_h2(q2.x), acc2);
            acc3 = __hfma2(w1, as_h2(q2.y), acc3);
            acc4 = __hfma2(w1, as_h2(q2.z), acc4);
            acc5 = __hfma2(w1, as_h2(q2.w), acc5);
        }
    }

    const float2 f0 = __half22float2(acc0);
    const float2 f1 = __half22float2(acc1);
    const float2 f2 = __half22float2(acc2);
    const float2 f3 = __half22float2(acc3);
    const float2 f4 = __half22float2(acc4);
    const float2 f5 = __half22float2(acc5);

    o0 = f0.x * r + f0.y * g + f1.x * b + f1.y;
    o1 = f2.x * r + f2.y * g + f3.x * b + f3.y;
    o2 = f4.x * r + f4.y * g + f5.x * b + f5.y;
}

__global__ void __launch_bounds__(512, 2)
bilateral_grid_u512_kernel(const float* __restrict__ pixels,
                           const float* __restrict__ coords,
                           const float* __restrict__ grid,
                           float* __restrict__ out,
                           int N)
{
    extern __shared__ __half sg[];

    // Convert fp32 grid -> fp16, write BOTH copies.
    {
        const float2* g2 = reinterpret_cast<const float2*>(grid);
        __half2* a2 = reinterpret_cast<__half2*>(sg);
        __half2* b2 = reinterpret_cast<__half2*>(sg + COPY_B_OFF);
        #pragma unroll 4
        for (int i = threadIdx.x; i < GRID_ELEMS / 2; i += 512) {
            const __half2 v = __float22half2_rn(g2[i]);
            a2[i] = v;
            b2[i] = v;
        }
    }
    __syncthreads();

    const int stride = gridDim.x * blockDim.x;
    const int tid0 = blockIdx.x * blockDim.x + threadIdx.x;

    // Unroll x2 with front-batched globals: iteration k+1's LDGs issue in
    // iteration k's LDS-wait shadow (cross-iteration MLP).
    int i = tid0;
    for (; i + stride < N; i += 2 * stride) {
        const int j = i + stride;

        const float r0 = pixels[3 * i + 0];
        const float g0 = pixels[3 * i + 1];
        const float b0 = pixels[3 * i + 2];
        const float2 c0 = reinterpret_cast<const float2*>(coords)[i];
        const float r1 = pixels[3 * j + 0];
        const float g1 = pixels[3 * j + 1];
        const float b1 = pixels[3 * j + 2];
        const float2 c1 = reinterpret_cast<const float2*>(coords)[j];

        float o0, o1, o2;
        process_pixel(sg, r0, g0, b0, c0.x, c0.y, o0, o1, o2);
        out[3 * i + 0] = o0;
        out[3 * i + 1] = o1;
        out[3 * i + 2] = o2;

        float p0, p1, p2;
        process_pixel(sg, r1, g1, b1, c1.x, c1.y, p0, p1, p2);
        out[3 * j + 0] = p0;
        out[3 * j + 1] = p1;
        out[3 * j + 2] = p2;
    }
    for (; i < N; i += stride) {
        const float r = pixels[3 * i + 0];
        const float g = pixels[3 * i + 1];
        const float b = pixels[3 * i + 2];
        const float2 c = reinterpret_cast<const float2*>(coords)[i];
        float o0, o1, o2;
        process_pixel(sg, r, g, b, c.x, c.y, o0, o1, o2);
        out[3 * i + 0] = o0;
        out[3 * i + 1] = o1;
        out[3 * i + 2] = o2;
    }
}

extern "C" void kernel_launch(void* const* d_in, const int* in_sizes, int n_in,
                              void* d_out, int out_size)
{
    const float* pixels = (const float*)d_in[0];   // (B,H,W,3) f32
    const float* coords = (const float*)d_in[1];   // (B,H,W,2) f32
    const float* grid   = (const float*)d_in[2];   // (16,16,8,12) f32
    float* out = (float*)d_out;

    const int N = in_sizes[0] / 3;

    cudaFuncSetAttribute(bilateral_grid_u512_kernel,
                         cudaFuncAttributeMaxDynamicSharedMemorySize, SMEM_BYTES);

    // 2 CTAs/SM x 152 SMs, 512 threads -> 32 warps/SM.
    const int blocks = 304;
    bilateral_grid_u512_kernel<<<blocks, 512, SMEM_BYTES>>>(pixels, coords, grid, out, N);
}